// round 2
// baseline (speedup 1.0000x reference)
#include <cuda_runtime.h>
#include <math.h>

#define BATCH   4
#define SEQ     501
#define BL      (BATCH*SEQ)     // 2004
#define NPOS    500
#define DM      256
#define DI      512
#define NLAYER  8

// ------------------------- scratch (device globals; no allocs) -------------------------
__device__ float g_h[BL*DM];
__device__ float g_xn[BL*DM];
__device__ float g_xcres[BL*1024];
__device__ float g_xc[BL*DI];
__device__ float g_xz[2L*BL*1024];
__device__ float g_u[2L*BL*DI];
__device__ float g_dbc[2L*BL*64];
__device__ float g_delta[2L*BL*DI];
__device__ float g_yg[2L*BL*DI];
__device__ float g_ym[2L*BL*DI];
__device__ float g_cat[BL*1024];

__device__ __forceinline__ float siluf(float x) { return x / (1.f + __expf(-x)); }
__device__ __forceinline__ float splusf(float x) { return x > 20.f ? x : log1pf(__expf(x)); }

// ------------------------- patch embedding (gemm with gathered A) -------------------------
// C[(b,p), c] = sum_{i<129,k<10} x[b,i,p*10+k] * pw[c,i,k] + pb[c] -> g_h[b*SEQ+1+p]
__global__ void patch_kernel(const float* __restrict__ x, const float* __restrict__ pw,
                             const float* __restrict__ pb)
{
    const int K = 1290;
    __shared__ float As[16][68];
    __shared__ float Ws[16][68];
    int tid = threadIdx.x;
    int tx = tid & 15, ty = tid >> 4;
    int bm = blockIdx.y * 64, bn = blockIdx.x * 64;
    int arow = tid >> 2;
    int akq = (tid & 3) << 2;

    int mload = bm + arow;
    bool mvalid = mload < 2000;
    int bb = mvalid ? (mload / NPOS) : 0;
    int ppos = mvalid ? (mload - bb * NPOS) : 0;
    const float* xbase = x + (long)bb * 129 * 5000 + ppos * 10;
    const float* wbase = pw + (long)(bn + arow) * K;

    float acc[4][4];
#pragma unroll
    for (int i = 0; i < 4; i++)
#pragma unroll
        for (int j = 0; j < 4; j++) acc[i][j] = 0.f;

    for (int k0 = 0; k0 < K; k0 += 16) {
#pragma unroll
        for (int j = 0; j < 4; j++) {
            int kk = k0 + akq + j;
            float a = 0.f, w = 0.f;
            if (kk < K) {
                if (mvalid) {
                    int i10 = kk / 10;
                    int r = kk - i10 * 10;
                    a = xbase[(long)i10 * 5000 + r];
                }
                w = wbase[kk];
            }
            As[akq + j][arow] = a;
            Ws[akq + j][arow] = w;
        }
        __syncthreads();
#pragma unroll
        for (int kk = 0; kk < 16; kk++) {
            float4 a4 = *reinterpret_cast<const float4*>(&As[kk][ty << 2]);
            float4 w4 = *reinterpret_cast<const float4*>(&Ws[kk][tx << 2]);
            acc[0][0] = fmaf(a4.x, w4.x, acc[0][0]); acc[0][1] = fmaf(a4.x, w4.y, acc[0][1]);
            acc[0][2] = fmaf(a4.x, w4.z, acc[0][2]); acc[0][3] = fmaf(a4.x, w4.w, acc[0][3]);
            acc[1][0] = fmaf(a4.y, w4.x, acc[1][0]); acc[1][1] = fmaf(a4.y, w4.y, acc[1][1]);
            acc[1][2] = fmaf(a4.y, w4.z, acc[1][2]); acc[1][3] = fmaf(a4.y, w4.w, acc[1][3]);
            acc[2][0] = fmaf(a4.z, w4.x, acc[2][0]); acc[2][1] = fmaf(a4.z, w4.y, acc[2][1]);
            acc[2][2] = fmaf(a4.z, w4.z, acc[2][2]); acc[2][3] = fmaf(a4.z, w4.w, acc[2][3]);
            acc[3][0] = fmaf(a4.w, w4.x, acc[3][0]); acc[3][1] = fmaf(a4.w, w4.y, acc[3][1]);
            acc[3][2] = fmaf(a4.w, w4.z, acc[3][2]); acc[3][3] = fmaf(a4.w, w4.w, acc[3][3]);
        }
        __syncthreads();
    }
#pragma unroll
    for (int i = 0; i < 4; i++) {
        int m = bm + (ty << 2) + i;
        if (m >= 2000) continue;
        int b = m / NPOS, p = m - (m / NPOS) * NPOS;
        long orow = ((long)b * SEQ + 1 + p) * DM;
#pragma unroll
        for (int j = 0; j < 4; j++) {
            int n = bn + (tx << 2) + j;
            g_h[orow + n] = acc[i][j] + pb[n];
        }
    }
}

__global__ void cls_kernel(const float* __restrict__ cls)
{
    int b = blockIdx.x;
    g_h[((long)b * SEQ) * DM + threadIdx.x] = cls[threadIdx.x];
}

// ------------------------- generic fp32 GEMM: C = A @ W^T (+epilogue) -------------------------
#define EPI_NONE     0
#define EPI_SOFTPLUS 1
#define EPI_RESID    2

template <int EPI>
__global__ void gemm_kernel(const float* __restrict__ A0, int lda, long sA,
                            const float* __restrict__ Wf, const float* __restrict__ Wb,
                            const float* __restrict__ bF, const float* __restrict__ bB,
                            float* C0, long sC,
                            const float* __restrict__ resid,
                            int M, int N, int K)
{
    const float* A = A0 + (long)blockIdx.z * sA;
    const float* W = blockIdx.z ? Wb : Wf;
    const float* bias = blockIdx.z ? bB : bF;
    float* C = C0 + (long)blockIdx.z * sC;

    __shared__ float As[16][68];
    __shared__ float Ws[16][68];
    int tid = threadIdx.x;
    int tx = tid & 15, ty = tid >> 4;
    int bm = blockIdx.y * 64, bn = blockIdx.x * 64;
    int arow = tid >> 2;
    int akq = (tid & 3) << 2;

    bool mvalid = (bm + arow) < M;
    const float* Aload = A + (long)(bm + arow) * lda + akq;
    const float* Wload = W + (long)(bn + arow) * K + akq;

    float acc[4][4];
#pragma unroll
    for (int i = 0; i < 4; i++)
#pragma unroll
        for (int j = 0; j < 4; j++) acc[i][j] = 0.f;

    for (int k0 = 0; k0 < K; k0 += 16) {
        float4 av = mvalid ? *reinterpret_cast<const float4*>(Aload + k0)
                           : make_float4(0.f, 0.f, 0.f, 0.f);
        float4 wv = *reinterpret_cast<const float4*>(Wload + k0);
        As[akq + 0][arow] = av.x; As[akq + 1][arow] = av.y;
        As[akq + 2][arow] = av.z; As[akq + 3][arow] = av.w;
        Ws[akq + 0][arow] = wv.x; Ws[akq + 1][arow] = wv.y;
        Ws[akq + 2][arow] = wv.z; Ws[akq + 3][arow] = wv.w;
        __syncthreads();
#pragma unroll
        for (int kk = 0; kk < 16; kk++) {
            float4 a4 = *reinterpret_cast<const float4*>(&As[kk][ty << 2]);
            float4 w4 = *reinterpret_cast<const float4*>(&Ws[kk][tx << 2]);
            acc[0][0] = fmaf(a4.x, w4.x, acc[0][0]); acc[0][1] = fmaf(a4.x, w4.y, acc[0][1]);
            acc[0][2] = fmaf(a4.x, w4.z, acc[0][2]); acc[0][3] = fmaf(a4.x, w4.w, acc[0][3]);
            acc[1][0] = fmaf(a4.y, w4.x, acc[1][0]); acc[1][1] = fmaf(a4.y, w4.y, acc[1][1]);
            acc[1][2] = fmaf(a4.y, w4.z, acc[1][2]); acc[1][3] = fmaf(a4.y, w4.w, acc[1][3]);
            acc[2][0] = fmaf(a4.z, w4.x, acc[2][0]); acc[2][1] = fmaf(a4.z, w4.y, acc[2][1]);
            acc[2][2] = fmaf(a4.z, w4.z, acc[2][2]); acc[2][3] = fmaf(a4.z, w4.w, acc[2][3]);
            acc[3][0] = fmaf(a4.w, w4.x, acc[3][0]); acc[3][1] = fmaf(a4.w, w4.y, acc[3][1]);
            acc[3][2] = fmaf(a4.w, w4.z, acc[3][2]); acc[3][3] = fmaf(a4.w, w4.w, acc[3][3]);
        }
        __syncthreads();
    }

#pragma unroll
    for (int i = 0; i < 4; i++) {
        int m = bm + (ty << 2) + i;
        if (m >= M) continue;
        int n0 = bn + (tx << 2);
        long off = (long)m * N + n0;
        float4 v = make_float4(acc[i][0], acc[i][1], acc[i][2], acc[i][3]);
        if (EPI == EPI_SOFTPLUS) {
            v.x = splusf(v.x + bias[n0 + 0]);
            v.y = splusf(v.y + bias[n0 + 1]);
            v.z = splusf(v.z + bias[n0 + 2]);
            v.w = splusf(v.w + bias[n0 + 3]);
        } else if (EPI == EPI_RESID) {
            float4 r = *reinterpret_cast<const float4*>(resid + off);
            v.x += r.x; v.y += r.y; v.z += r.z; v.w += r.w;
        }
        *reinterpret_cast<float4*>(C + off) = v;
    }
}

// ------------------------- causal depthwise conv (K=4) + SiLU -------------------------
// forward:  y[t] = b + sum_k x[t+k-3]*w[k]   (left zero pad)
// backward (dir==1 && rev_dir1): y[t] = b + sum_k x[t+3-k]*w[k]  (right zero pad)
__global__ void conv_silu_kernel(const float* __restrict__ X0, long sX, int xpitch,
                                 const float* __restrict__ wF, const float* __restrict__ wB,
                                 const float* __restrict__ bF, const float* __restrict__ bB,
                                 float* Y0, long sY, int rev_dir1)
{
    int dir = blockIdx.z;
    const float* X = X0 + (long)dir * sX;
    const float* w = dir ? wB : wF;
    const float* bias = dir ? bB : bF;
    float* Y = Y0 + (long)dir * sY;
    int rev = dir & rev_dir1;

    int idx = blockIdx.x * blockDim.x + threadIdx.x;
    if (idx >= BL * DI) return;
    int d = idx & (DI - 1);
    int m = idx >> 9;
    int b = m / SEQ, l = m - b * SEQ;

    float acc = bias[d];
#pragma unroll
    for (int k = 0; k < 4; k++) {
        int ll = rev ? (l + 3 - k) : (l + k - 3);
        if (ll >= 0 && ll < SEQ)
            acc = fmaf(X[((long)(b * SEQ + ll)) * xpitch + d], w[d * 4 + k], acc);
    }
    Y[(long)m * DI + d] = siluf(acc);
}

// ------------------------- selective scan (both directions in one launch) -------------------------
__global__ void scan_kernel(const float* __restrict__ Alf, const float* __restrict__ Alb,
                            const float* __restrict__ Df,  const float* __restrict__ Db)
{
    int tid = threadIdx.x;
    int g = blockIdx.x * 16 + (tid >> 4);
    int n = tid & 15;
    int dir = g >> 11;
    int b = (g >> 9) & 3;
    int d = g & 511;

    const float* Al = dir ? Alb : Alf;
    const float* Dp = dir ? Db : Df;
    float Acoef = -__expf(Al[d * 16 + n]);
    float Dv = Dp[d];

    const float* u     = g_u     + (long)dir * BL * DI;
    const float* delta = g_delta + (long)dir * BL * DI;
    const float* dbc   = g_dbc   + (long)dir * BL * 64;
    const float* zb    = g_xz    + (long)dir * BL * 1024 + DI;   // z half of in-proj
    float* yg          = g_yg    + (long)dir * BL * DI;

    float h = 0.f;
    for (int tt = 0; tt < SEQ; tt++) {
        int t = dir ? (SEQ - 1 - tt) : tt;
        long m = (long)b * SEQ + t;
        float dv = delta[m * DI + d];
        float uv = u[m * DI + d];
        float Bv = dbc[m * 64 + 32 + n];
        float Cv = dbc[m * 64 + 48 + n];
        float dA = __expf(dv * Acoef);
        h = fmaf(dA, h, dv * Bv * uv);
        float p = h * Cv;
        p += __shfl_xor_sync(0xffffffffu, p, 8);
        p += __shfl_xor_sync(0xffffffffu, p, 4);
        p += __shfl_xor_sync(0xffffffffu, p, 2);
        p += __shfl_xor_sync(0xffffffffu, p, 1);
        if (n == 0) {
            float zv = zb[m * 1024 + d];
            yg[m * DI + d] = (p + uv * Dv) * siluf(zv);
        }
    }
}

// ------------------------- gate + concat -------------------------
__global__ void gate_cat_kernel()
{
    long idx = (long)blockIdx.x * blockDim.x + threadIdx.x;
    if (idx >= (long)BL * 1024) return;
    int j = (int)(idx & 1023);
    long m = idx >> 10;
    int dirr = j >> 9;
    int d = j & 511;
    float res = g_xcres[m * 1024 + 512 + d];
    g_cat[idx] = g_ym[(long)dirr * BL * DI + m * DI + d] * siluf(res);
}

// ------------------------- layernorm (256 wide) -------------------------
__global__ void ln_kernel(const float* __restrict__ X, const float* __restrict__ gg,
                          const float* __restrict__ bb, float* __restrict__ Y, int rowStride)
{
    int row = blockIdx.x * rowStride;
    int tid = threadIdx.x;
    float v = X[(long)row * DM + tid];
    float s = v, sq = v * v;
#pragma unroll
    for (int o = 16; o > 0; o >>= 1) {
        s  += __shfl_xor_sync(0xffffffffu, s, o);
        sq += __shfl_xor_sync(0xffffffffu, sq, o);
    }
    __shared__ float ss[8], sq2[8];
    int wid = tid >> 5, lane = tid & 31;
    if (lane == 0) { ss[wid] = s; sq2[wid] = sq; }
    __syncthreads();
    float ts = 0.f, tq = 0.f;
#pragma unroll
    for (int i = 0; i < 8; i++) { ts += ss[i]; tq += sq2[i]; }
    float mean = ts * (1.f / DM);
    float var = tq * (1.f / DM) - mean * mean;
    float inv = rsqrtf(var + 1e-5f);
    Y[(long)blockIdx.x * DM + tid] = (v - mean) * inv * gg[tid] + bb[tid];
}

// ------------------------- host orchestration -------------------------
extern "C" void kernel_launch(void* const* d_in, const int* in_sizes, int n_in,
                              void* d_out, int out_size)
{
    // Input binding. Two candidate orders exist:
    //  - dict order (setup_inputs insertion order):
    //      x, patch_w, patch_b, cls, ln_g, ln_b, in_w, cw, cb, out_w, fn_g, fn_b,
    //      mf_in..mf_ow, mb_in..mb_ow
    //  - signature order (reference() params):
    //      x, patch_w, patch_b, cls, ln_g, ln_b, in_w, cw, cb,
    //      mf_in..mf_ow, mb_in..mb_ow, out_w, fn_g, fn_b
    // Disambiguate via in_sizes[9]: dict -> out_w (8*256*1024 = 2097152),
    //                               sig  -> mf_in (8*1024*512 = 4194304).
    const bool sig_order = (in_sizes[9] == 8 * 1024 * 512);

    const float* x       = (const float*)d_in[0];
    const float* patch_w = (const float*)d_in[1];
    const float* patch_b = (const float*)d_in[2];
    const float* cls     = (const float*)d_in[3];
    const float* ln_g    = (const float*)d_in[4];
    const float* ln_b    = (const float*)d_in[5];
    const float* in_w    = (const float*)d_in[6];
    const float* cw      = (const float*)d_in[7];
    const float* cb      = (const float*)d_in[8];

    const float *out_w, *fn_g, *fn_b;
    const float *mf_in, *mf_cw, *mf_cb, *mf_xp, *mf_dtw, *mf_dtb, *mf_Al, *mf_D, *mf_ow;
    const float *mb_in, *mb_cw, *mb_cb, *mb_xp, *mb_dtw, *mb_dtb, *mb_Al, *mb_D, *mb_ow;

    if (sig_order) {
        mf_in  = (const float*)d_in[9];  mf_cw  = (const float*)d_in[10];
        mf_cb  = (const float*)d_in[11]; mf_xp  = (const float*)d_in[12];
        mf_dtw = (const float*)d_in[13]; mf_dtb = (const float*)d_in[14];
        mf_Al  = (const float*)d_in[15]; mf_D   = (const float*)d_in[16];
        mf_ow  = (const float*)d_in[17];
        mb_in  = (const float*)d_in[18]; mb_cw  = (const float*)d_in[19];
        mb_cb  = (const float*)d_in[20]; mb_xp  = (const float*)d_in[21];
        mb_dtw = (const float*)d_in[22]; mb_dtb = (const float*)d_in[23];
        mb_Al  = (const float*)d_in[24]; mb_D   = (const float*)d_in[25];
        mb_ow  = (const float*)d_in[26];
        out_w  = (const float*)d_in[27];
        fn_g   = (const float*)d_in[28]; fn_b   = (const float*)d_in[29];
    } else {
        out_w  = (const float*)d_in[9];
        fn_g   = (const float*)d_in[10]; fn_b   = (const float*)d_in[11];
        mf_in  = (const float*)d_in[12]; mf_cw  = (const float*)d_in[13];
        mf_cb  = (const float*)d_in[14]; mf_xp  = (const float*)d_in[15];
        mf_dtw = (const float*)d_in[16]; mf_dtb = (const float*)d_in[17];
        mf_Al  = (const float*)d_in[18]; mf_D   = (const float*)d_in[19];
        mf_ow  = (const float*)d_in[20];
        mb_in  = (const float*)d_in[21]; mb_cw  = (const float*)d_in[22];
        mb_cb  = (const float*)d_in[23]; mb_xp  = (const float*)d_in[24];
        mb_dtw = (const float*)d_in[25]; mb_dtb = (const float*)d_in[26];
        mb_Al  = (const float*)d_in[27]; mb_D   = (const float*)d_in[28];
        mb_ow  = (const float*)d_in[29];
    }

    float *p_h, *p_xn, *p_xcres, *p_xc, *p_xz, *p_u, *p_dbc, *p_delta, *p_yg, *p_ym, *p_cat;
    cudaGetSymbolAddress((void**)&p_h, g_h);
    cudaGetSymbolAddress((void**)&p_xn, g_xn);
    cudaGetSymbolAddress((void**)&p_xcres, g_xcres);
    cudaGetSymbolAddress((void**)&p_xc, g_xc);
    cudaGetSymbolAddress((void**)&p_xz, g_xz);
    cudaGetSymbolAddress((void**)&p_u, g_u);
    cudaGetSymbolAddress((void**)&p_dbc, g_dbc);
    cudaGetSymbolAddress((void**)&p_delta, g_delta);
    cudaGetSymbolAddress((void**)&p_yg, g_yg);
    cudaGetSymbolAddress((void**)&p_ym, g_ym);
    cudaGetSymbolAddress((void**)&p_cat, g_cat);

    const int MT = (BL + 63) / 64;  // 32 row tiles
    const long sXZ = (long)BL * 1024;
    const long sDI = (long)BL * DI;
    const long sDBC = (long)BL * 64;

    // patch embed + cls token
    patch_kernel<<<dim3(DM / 64, (2000 + 63) / 64), 256>>>(x, patch_w, patch_b);
    cls_kernel<<<BATCH, DM>>>(cls);

    for (int l = 0; l < NLAYER; l++) {
        // 1) layernorm
        ln_kernel<<<BL, DM>>>(p_h, ln_g + l * 256, ln_b + l * 256, p_xn, 1);
        // 2) block in-proj: xn(2004x256) @ in_w^T -> xcres(2004x1024)
        gemm_kernel<EPI_NONE><<<dim3(1024 / 64, MT, 1), 256>>>(
            p_xn, 256, 0, in_w + (long)l * 1024 * 256, in_w + (long)l * 1024 * 256,
            nullptr, nullptr, p_xcres, 0, nullptr, BL, 1024, 256);
        // 3) block conv+silu (forward only): xcres[:, :512] -> xc
        conv_silu_kernel<<<dim3((BL * DI + 255) / 256, 1, 1), 256>>>(
            p_xcres, 0, 1024, cw + l * 2048, cw + l * 2048, cb + l * 512, cb + l * 512,
            p_xc, 0, 0);
        // 4) mamba in-proj (both dirs): xc @ {mf,mb}_in^T -> xz[2]
        gemm_kernel<EPI_NONE><<<dim3(1024 / 64, MT, 2), 256>>>(
            p_xc, 512, 0, mf_in + (long)l * 1024 * 512, mb_in + (long)l * 1024 * 512,
            nullptr, nullptr, p_xz, sXZ, nullptr, BL, 1024, 512);
        // 5) mamba conv+silu (dir-aware): xz[dir][:, :512] -> u[dir]
        conv_silu_kernel<<<dim3((BL * DI + 255) / 256, 1, 2), 256>>>(
            p_xz, sXZ, 1024, mf_cw + l * 2048, mb_cw + l * 2048,
            mf_cb + l * 512, mb_cb + l * 512, p_u, sDI, 1);
        // 6) x-proj: u @ xp^T -> dbc (dt|B|C)
        gemm_kernel<EPI_NONE><<<dim3(1, MT, 2), 256>>>(
            p_u, 512, sDI, mf_xp + (long)l * 64 * 512, mb_xp + (long)l * 64 * 512,
            nullptr, nullptr, p_dbc, sDBC, nullptr, BL, 64, 512);
        // 7) delta = softplus(dt @ dtw^T + dtb)
        gemm_kernel<EPI_SOFTPLUS><<<dim3(512 / 64, MT, 2), 256>>>(
            p_dbc, 64, sDBC, mf_dtw + (long)l * 512 * 32, mb_dtw + (long)l * 512 * 32,
            mf_dtb + l * 512, mb_dtb + l * 512, p_delta, sDI, nullptr, BL, 512, 32);
        // 8) selective scan (+u*D, *silu(z)) both dirs -> yg
        scan_kernel<<<256, 256>>>(mf_Al + l * 8192, mb_Al + l * 8192,
                                  mf_D + l * 512, mb_D + l * 512);
        // 9) out-proj: yg @ ow^T -> ym
        gemm_kernel<EPI_NONE><<<dim3(512 / 64, MT, 2), 256>>>(
            p_yg, 512, sDI, mf_ow + (long)l * 512 * 512, mb_ow + (long)l * 512 * 512,
            nullptr, nullptr, p_ym, sDI, nullptr, BL, 512, 512);
        // 10) gate + concat: cat = [ym_f*silu(res), ym_b*silu(res)]
        gate_cat_kernel<<<(int)(((long)BL * 1024 + 255) / 256), 256>>>();
        // 11) block out-proj + residual: h = cat @ out_w^T + h
        gemm_kernel<EPI_RESID><<<dim3(DM / 64, MT, 1), 256>>>(
            p_cat, 1024, 0, out_w + (long)l * 256 * 1024, out_w + (long)l * 256 * 1024,
            nullptr, nullptr, p_h, 0, p_h, BL, DM, 1024);
    }

    // final layernorm on cls rows -> output (4 x 256)
    ln_kernel<<<BATCH, DM>>>(p_h, fn_g, fn_b, (float*)d_out, SEQ);
}